// round 8
// baseline (speedup 1.0000x reference)
#include <cuda_runtime.h>
#include <cstdint>

#define T_ 512
#define H_ 2048
#define F_ 768
#define E_ 64
#define K_ 8
#define KC 16   // K per chunk
#define KW 12   // padded word-stride of split planes (8 used + 4 pad) -> conflict-free LDS

// ---------------- scratch (static __device__, allocation-free) ----------------
__device__ int   g_cnt[E_];
__device__ int   g_off[E_];
__device__ int   g_tok[E_][T_];
__device__ float g_cw [E_][T_];
__device__ float g_h  [(size_t)T_ * K_ * F_];   // 12.6 MB compact slab

// ---------------- helpers ----------------
__device__ __forceinline__ unsigned short f2bf(float v) {
    unsigned short r; asm("cvt.rn.bf16.f32 %0, %1;" : "=h"(r) : "f"(v)); return r;
}
__device__ __forceinline__ float bf2f(unsigned short b) {
    return __uint_as_float(((unsigned)b) << 16);
}
// split two consecutive fp32 into packed bf16x2 hi / lo words (elem0 in low half)
__device__ __forceinline__ void bfsplit2(float v0, float v1, unsigned& hi, unsigned& lo) {
    unsigned short h0 = f2bf(v0), h1 = f2bf(v1);
    unsigned short l0 = f2bf(v0 - bf2f(h0)), l1 = f2bf(v1 - bf2f(h1));
    hi = ((unsigned)h1 << 16) | h0;
    lo = ((unsigned)l1 << 16) | l0;
}
// single-element split (for B scatter stores)
__device__ __forceinline__ void bfsplit1(float v, unsigned short& h, unsigned short& l) {
    h = f2bf(v);
    l = f2bf(v - bf2f(h));
}
__device__ __forceinline__ void mma_bf16(float c[4],
    unsigned a0, unsigned a1, unsigned a2, unsigned a3,
    unsigned b0, unsigned b1) {
    asm volatile(
        "mma.sync.aligned.m16n8k16.row.col.f32.bf16.bf16.f32 "
        "{%0,%1,%2,%3}, {%4,%5,%6,%7}, {%8,%9}, {%0,%1,%2,%3};\n"
        : "+f"(c[0]), "+f"(c[1]), "+f"(c[2]), "+f"(c[3])
        : "r"(a0), "r"(a1), "r"(a2), "r"(a3), "r"(b0), "r"(b1));
}

// ---------------- kernel 0: zero output + counters ----------------
__global__ void k_zero(float* __restrict__ out) {
    int i = blockIdx.x * 256 + threadIdx.x;
    if (i < T_ * H_) out[i] = 0.f;
    if (i < E_) g_cnt[i] = 0;
}

// ---------------- kernel 1: router, 4 tokens/block ----------------
__global__ void k_router(const float* __restrict__ x, const float* __restrict__ gw) {
    __shared__ float sx[4][H_];
    __shared__ float slog[4][E_];
    const int t0 = blockIdx.x * 4;
    const int tid = threadIdx.x;            // 64 threads, one expert each

#pragma unroll
    for (int j = 0; j < 4; j++) {
        const float4* xr = (const float4*)(x + (size_t)(t0 + j) * H_);
        float4* s4 = (float4*)sx[j];
        for (int i = tid; i < H_ / 4; i += 64) s4[i] = xr[i];
    }
    __syncthreads();

    const float4* g4 = (const float4*)(gw + (size_t)tid * H_);
    const float4* s0 = (const float4*)sx[0];
    const float4* s1 = (const float4*)sx[1];
    const float4* s2 = (const float4*)sx[2];
    const float4* s3 = (const float4*)sx[3];
    float a0 = 0.f, a1 = 0.f, a2 = 0.f, a3 = 0.f;
    for (int i = 0; i < H_ / 4; i++) {
        float4 b = g4[i];
        float4 v0 = s0[i]; a0 += v0.x*b.x + v0.y*b.y + v0.z*b.z + v0.w*b.w;
        float4 v1 = s1[i]; a1 += v1.x*b.x + v1.y*b.y + v1.z*b.z + v1.w*b.w;
        float4 v2 = s2[i]; a2 += v2.x*b.x + v2.y*b.y + v2.z*b.z + v2.w*b.w;
        float4 v3 = s3[i]; a3 += v3.x*b.x + v3.y*b.y + v3.z*b.z + v3.w*b.w;
    }
    slog[0][tid] = a0; slog[1][tid] = a1; slog[2][tid] = a2; slog[3][tid] = a3;
    __syncthreads();

    if (tid < 4) {
        const int t = t0 + tid;
        const float* sl = slog[tid];
        int ids[K_]; float lv[K_];
        unsigned long long mask = 0;
        for (int j = 0; j < K_; j++) {
            float best = -1e30f; int bi = 0;
            for (int e = 0; e < E_; e++) {
                if (!((mask >> e) & 1ull) && sl[e] > best) { best = sl[e]; bi = e; }
            }
            mask |= 1ull << bi; ids[j] = bi; lv[j] = best;
        }
        float m = lv[0], s = 0.f, w[K_];
        for (int j = 0; j < K_; j++) { w[j] = __expf(lv[j] - m); s += w[j]; }
        float inv = 1.f / s;
        for (int j = 0; j < K_; j++) {
            int e = ids[j];
            int slot = atomicAdd(&g_cnt[e], 1);
            g_tok[e][slot] = t;
            g_cw [e][slot] = w[j] * inv;
        }
    }
}

// ---------------- kernel 1b: exclusive scan of counts -> slab offsets ----------------
__global__ void k_scan() {
    if (threadIdx.x == 0) {
        int acc = 0;
        for (int e = 0; e < E_; e++) { g_off[e] = acc; acc += g_cnt[e]; }
    }
}

// =====================================================================
// GEMM kernels: bf16 Ootomo 3-MMA (Ah*Bh + Al*Bh + Ah*Bl), fp32 accum.
// Split planes in smem as packed bf16x2 words, stride KW=12 (conflict-free).
// A plane: [64 rows][KW words]; B plane: [128 cols][KW words] ("[n][k]").
// Double buffer, register prefetch one chunk ahead, one barrier per chunk.
// =====================================================================

// ---------------- kernel 2: grouped GEMM1 (gate|up fused) + SwiGLU ----------------
__global__ __launch_bounds__(256) void k_gemm1(const float* __restrict__ x,
                                               const float* __restrict__ wg,
                                               const float* __restrict__ wu) {
    const int e  = blockIdx.z;
    const int Ne = g_cnt[e];
    const int m0 = blockIdx.y * 64;
    if (m0 >= Ne) return;
    const int n0 = blockIdx.x * 64;

    __shared__ union {
        struct {
            unsigned Ah[2][64][KW];    // 6144 B
            unsigned Al[2][64][KW];    // 6144 B
            unsigned Bh[2][128][KW];   // 12288 B
            unsigned Bl[2][128][KW];   // 12288 B
        } p;                            // 36864 B
        float ep[64][132];              // epilogue alias (33792 B)
    } sm;

    const int tid  = threadIdx.x;
    const int lane = tid & 31, wid = tid >> 5;
    const int mw = (wid >> 2) * 32;   // 0 / 32
    const int nw = (wid & 3) * 32;    // 0..96

    // A loader: thread -> (row, 4 consecutive k)
    const int arow = tid >> 2;
    const int aq   = tid & 3;          // k quad: k = aq*4 .. aq*4+3
    const bool avalid = (m0 + arow) < Ne;
    const int tok = avalid ? g_tok[e][m0 + arow] : 0;
    const float4* xrow = (const float4*)(x + (size_t)tok * H_);

    // B loader: thread -> (k row bk, 4 consecutive n) for gate AND up
    const int bk  = tid >> 4;          // 0..15
    const int bn4 = (tid & 15) * 4;    // 0..60
    const size_t ebase = (size_t)e * H_ * F_;
    const float* wgB = wg + ebase + (size_t)bk * F_ + n0 + bn4;
    const float* wuB = wu + ebase + (size_t)bk * F_ + n0 + bn4;

    float acc[2][4][4];
#pragma unroll
    for (int mi = 0; mi < 2; mi++)
#pragma unroll
        for (int ni = 0; ni < 4; ni++)
#pragma unroll
            for (int f = 0; f < 4; f++) acc[mi][ni][f] = 0.f;

    float4 rA, rG, rU;
    const float4 f40 = make_float4(0.f, 0.f, 0.f, 0.f);

    auto ld = [&](int kt) {
        rA = avalid ? xrow[kt * (KC / 4) + aq] : f40;
        rG = *(const float4*)(wgB + (size_t)kt * KC * F_);
        rU = *(const float4*)(wuB + (size_t)kt * KC * F_);
    };
    auto st = [&](int buf) {
        // A: two packed words per plane
        unsigned h0, l0, h1, l1;
        bfsplit2(rA.x, rA.y, h0, l0);
        bfsplit2(rA.z, rA.w, h1, l1);
        sm.p.Ah[buf][arow][aq * 2    ] = h0;
        sm.p.Ah[buf][arow][aq * 2 + 1] = h1;
        sm.p.Al[buf][arow][aq * 2    ] = l0;
        sm.p.Al[buf][arow][aq * 2 + 1] = l1;
        // B: scatter 16-bit into [n][k] planes (gate cols 0-63, up cols 64-127)
        unsigned short* bh = (unsigned short*)&sm.p.Bh[buf][0][0];
        unsigned short* bl = (unsigned short*)&sm.p.Bl[buf][0][0];
        const float gv[4] = { rG.x, rG.y, rG.z, rG.w };
        const float uv[4] = { rU.x, rU.y, rU.z, rU.w };
#pragma unroll
        for (int j = 0; j < 4; j++) {
            unsigned short h, l;
            int ng = bn4 + j;
            bfsplit1(gv[j], h, l);
            bh[ng * (2 * KW) + bk] = h;  bl[ng * (2 * KW) + bk] = l;
            int nu = 64 + bn4 + j;
            bfsplit1(uv[j], h, l);
            bh[nu * (2 * KW) + bk] = h;  bl[nu * (2 * KW) + bk] = l;
        }
    };
    auto compute = [&](int buf) {
        unsigned ah[2][4], al[2][4], bh[4][2], bl[4][2];
        const int c = lane & 3;
#pragma unroll
        for (int mi = 0; mi < 2; mi++) {
            const int r = mw + mi * 16 + (lane >> 2);
            ah[mi][0] = sm.p.Ah[buf][r    ][c];
            ah[mi][1] = sm.p.Ah[buf][r + 8][c];
            ah[mi][2] = sm.p.Ah[buf][r    ][c + 4];
            ah[mi][3] = sm.p.Ah[buf][r + 8][c + 4];
            al[mi][0] = sm.p.Al[buf][r    ][c];
            al[mi][1] = sm.p.Al[buf][r + 8][c];
            al[mi][2] = sm.p.Al[buf][r    ][c + 4];
            al[mi][3] = sm.p.Al[buf][r + 8][c + 4];
        }
#pragma unroll
        for (int ni = 0; ni < 4; ni++) {
            const int n = nw + ni * 8 + (lane >> 2);
            bh[ni][0] = sm.p.Bh[buf][n][c];
            bh[ni][1] = sm.p.Bh[buf][n][c + 4];
            bl[ni][0] = sm.p.Bl[buf][n][c];
            bl[ni][1] = sm.p.Bl[buf][n][c + 4];
        }
#pragma unroll
        for (int mi = 0; mi < 2; mi++)
#pragma unroll
            for (int ni = 0; ni < 4; ni++) {
                mma_bf16(acc[mi][ni], ah[mi][0], ah[mi][1], ah[mi][2], ah[mi][3],
                         bh[ni][0], bh[ni][1]);
                mma_bf16(acc[mi][ni], al[mi][0], al[mi][1], al[mi][2], al[mi][3],
                         bh[ni][0], bh[ni][1]);
                mma_bf16(acc[mi][ni], ah[mi][0], ah[mi][1], ah[mi][2], ah[mi][3],
                         bl[ni][0], bl[ni][1]);
            }
    };

    const int NK = H_ / KC;   // 128
    ld(0); st(0); __syncthreads();
    for (int kt = 0; kt < NK; kt++) {
        const int cur = kt & 1;
        if (kt + 1 < NK) ld(kt + 1);
        compute(cur);
        if (kt + 1 < NK) st(cur ^ 1);
        __syncthreads();
    }

    // epilogue: exchange gate/up via smem, SwiGLU * combine weight -> g_h
#pragma unroll
    for (int mi = 0; mi < 2; mi++)
#pragma unroll
        for (int ni = 0; ni < 4; ni++)
#pragma unroll
            for (int f = 0; f < 4; f++) {
                int r = mw + mi * 16 + (lane >> 2) + ((f >= 2) ? 8 : 0);
                int c = nw + ni * 8 + (lane & 3) * 2 + (f & 1);
                sm.ep[r][c] = acc[mi][ni][f];
            }
    __syncthreads();

    float* hout = g_h + ((size_t)(g_off[e] + m0)) * F_ + n0;
    for (int i = tid; i < 64 * 64; i += 256) {
        int m = i >> 6, n = i & 63;
        if (m0 + m < Ne) {
            float g = sm.ep[m][n], u = sm.ep[m][64 + n];
            float sg = g / (1.f + __expf(-g));
            hout[(size_t)m * F_ + n] = sg * u * g_cw[e][m0 + m];
        }
    }
}

// ---------------- kernel 3: grouped GEMM2 (h @ w_down), atomic combine ----------------
__global__ __launch_bounds__(256) void k_gemm2(const float* __restrict__ wd,
                                               float* __restrict__ out) {
    const int e  = blockIdx.z;
    const int Ne = g_cnt[e];
    const int m0 = blockIdx.y * 64;
    if (m0 >= Ne) return;
    const int n0 = blockIdx.x * 128;

    __shared__ struct {
        unsigned Ah[2][64][KW];
        unsigned Al[2][64][KW];
        unsigned Bh[2][128][KW];
        unsigned Bl[2][128][KW];
    } sm;

    const int tid  = threadIdx.x;
    const int lane = tid & 31, wid = tid >> 5;
    const int mw = (wid >> 2) * 32;
    const int nw = (wid & 3) * 32;

    const int arow = tid >> 2;
    const int aq   = tid & 3;
    const bool avalid = (m0 + arow) < Ne;
    const int hr = g_off[e] + (avalid ? (m0 + arow) : 0);
    const float4* hrow = (const float4*)(g_h + (size_t)hr * F_);

    // B loader: two k-rows per thread: bk0 (0..7), bk1 = bk0+8; 4 consecutive n
    const int bk0 = tid >> 5;          // 0..7
    const int bk1 = bk0 + 8;
    const int bn4 = (tid & 31) * 4;    // 0..124
    const float* wdB = wd + (size_t)e * F_ * H_ + n0 + bn4;

    float acc[2][4][4];
#pragma unroll
    for (int mi = 0; mi < 2; mi++)
#pragma unroll
        for (int ni = 0; ni < 4; ni++)
#pragma unroll
            for (int f = 0; f < 4; f++) acc[mi][ni][f] = 0.f;

    float4 rA, rB0, rB1;
    const float4 f40 = make_float4(0.f, 0.f, 0.f, 0.f);

    auto ld = [&](int kt) {
        rA  = avalid ? hrow[kt * (KC / 4) + aq] : f40;
        rB0 = *(const float4*)(wdB + (size_t)(kt * KC + bk0) * H_);
        rB1 = *(const float4*)(wdB + (size_t)(kt * KC + bk1) * H_);
    };
    auto st = [&](int buf) {
        unsigned h0, l0, h1, l1;
        bfsplit2(rA.x, rA.y, h0, l0);
        bfsplit2(rA.z, rA.w, h1, l1);
        sm.Ah[buf][arow][aq * 2    ] = h0;
        sm.Ah[buf][arow][aq * 2 + 1] = h1;
        sm.Al[buf][arow][aq * 2    ] = l0;
        sm.Al[buf][arow][aq * 2 + 1] = l1;
        unsigned short* bh = (unsigned short*)&sm.Bh[buf][0][0];
        unsigned short* bl = (unsigned short*)&sm.Bl[buf][0][0];
        const float v0[4] = { rB0.x, rB0.y, rB0.z, rB0.w };
        const float v1[4] = { rB1.x, rB1.y, rB1.z, rB1.w };
#pragma unroll
        for (int j = 0; j < 4; j++) {
            unsigned short h, l;
            int n = bn4 + j;
            bfsplit1(v0[j], h, l);
            bh[n * (2 * KW) + bk0] = h;  bl[n * (2 * KW) + bk0] = l;
            bfsplit1(v1[j], h, l);
            bh[n * (2 * KW) + bk1] = h;  bl[n * (2 * KW) + bk1] = l;
        }
    };
    auto compute = [&](int buf) {
        unsigned ah[2][4], al[2][4], bh[4][2], bl[4][2];
        const int c = lane & 3;
#pragma unroll
        for (int mi = 0; mi < 2; mi++) {
            const int r = mw + mi * 16 + (lane >> 2);
            ah[mi][0] = sm.Ah[buf][r    ][c];
            ah[mi][1] = sm.Ah[buf][r + 8][c];
            ah[mi][2] = sm.Ah[buf][r    ][c + 4];
            ah[mi][3] = sm.Ah[buf][r + 8][c + 4];
            al[mi][0] = sm.Al[buf][r    ][c];
            al[mi][1] = sm.Al[buf][r + 8][c];
            al[mi][2] = sm.Al[buf][r    ][c + 4];
            al[mi][3] = sm.Al[buf][r + 8][c + 4];
        }
#pragma unroll
        for (int ni = 0; ni < 4; ni++) {
            const int n = nw + ni * 8 + (lane >> 2);
            bh[ni][0] = sm.Bh[buf][n][c];
            bh[ni][1] = sm.Bh[buf][n][c + 4];
            bl[ni][0] = sm.Bl[buf][n][c];
            bl[ni][1] = sm.Bl[buf][n][c + 4];
        }
#pragma unroll
        for (int mi = 0; mi < 2; mi++)
#pragma unroll
            for (int ni = 0; ni < 4; ni++) {
                mma_bf16(acc[mi][ni], ah[mi][0], ah[mi][1], ah[mi][2], ah[mi][3],
                         bh[ni][0], bh[ni][1]);
                mma_bf16(acc[mi][ni], al[mi][0], al[mi][1], al[mi][2], al[mi][3],
                         bh[ni][0], bh[ni][1]);
                mma_bf16(acc[mi][ni], ah[mi][0], ah[mi][1], ah[mi][2], ah[mi][3],
                         bl[ni][0], bl[ni][1]);
            }
    };

    const int NK = F_ / KC;   // 48
    ld(0); st(0); __syncthreads();
    for (int kt = 0; kt < NK; kt++) {
        const int cur = kt & 1;
        if (kt + 1 < NK) ld(kt + 1);
        compute(cur);
        if (kt + 1 < NK) st(cur ^ 1);
        __syncthreads();
    }

    // epilogue: atomic accumulate into out rows (token per M-row)
    int toks[2][2];
#pragma unroll
    for (int mi = 0; mi < 2; mi++)
#pragma unroll
        for (int ro = 0; ro < 2; ro++) {
            int r = m0 + mw + mi * 16 + (lane >> 2) + ro * 8;
            toks[mi][ro] = (r < Ne) ? g_tok[e][r] : -1;
        }
#pragma unroll
    for (int mi = 0; mi < 2; mi++)
#pragma unroll
        for (int ni = 0; ni < 4; ni++)
#pragma unroll
            for (int f = 0; f < 4; f++) {
                int tok = toks[mi][f >> 1];
                if (tok >= 0) {
                    int c = n0 + nw + ni * 8 + (lane & 3) * 2 + (f & 1);
                    atomicAdd(&out[(size_t)tok * H_ + c], acc[mi][ni][f]);
                }
            }
}

// ---------------- launch ----------------
extern "C" void kernel_launch(void* const* d_in, const int* in_sizes, int n_in,
                              void* d_out, int out_size) {
    const float* x     = (const float*)d_in[0];
    const float* gw    = (const float*)d_in[1];
    const float* wgate = (const float*)d_in[2];
    const float* wup   = (const float*)d_in[3];
    const float* wdown = (const float*)d_in[4];
    float* out = (float*)d_out;

    k_zero<<<(T_ * H_ + 255) / 256, 256>>>(out);
    k_router<<<T_ / 4, 64>>>(x, gw);
    k_scan<<<1, 32>>>();
    k_gemm1<<<dim3(F_ / 64, T_ / 64, E_), 256>>>(x, wgate, wup);
    k_gemm2<<<dim3(H_ / 128, T_ / 64, E_), 256>>>(wdown, out);
}